// round 13
// baseline (speedup 1.0000x reference)
#include <cuda_runtime.h>

#define T_STEPS 2048
#define BATCH   256
#define DIN     128
#define NG      16      // scratch layout k = u*4 + g
#define RDEPTH  4

#define RECUR_BLOCKS  32
#define TOTAL_BLOCKS  148
#define PROJ_TILES    (T_STEPS * BATCH / 64)   // 8192
#define FUSED_THREADS 256

// Scratch: x-part projections (+bias+theta folded), layout [t][b][u*4+g]
// Over-allocated by RDEPTH steps so the recurrence prefetch needs no bounds check.
__device__ float g_xproj[(T_STEPS + RDEPTH) * BATCH * NG];
// per-t completion counters (4 proj tiles per t); tail pre-set to "done"
__device__ int g_done[T_STEPS + 16];
// persistent-proj work counter
__device__ int g_tile;

// ---------------------------------------------------------------------------
__global__ void clear_kernel()
{
    int i = blockIdx.x * blockDim.x + threadIdx.x;
    if (i < T_STEPS + 16)
        g_done[i] = (i < T_STEPS) ? 0 : 4;
    if (i == 0)
        g_tile = 0;
}

// ---------------------------------------------------------------------------
// helpers
// ---------------------------------------------------------------------------
__device__ __forceinline__ float tanh_a(float x) {
    float y;
    asm("tanh.approx.f32 %0, %1;" : "=f"(y) : "f"(x));
    return y;
}
// sigmoid on [-1,1] via odd Taylor poly (err <= ~3e-6): fixed-latency FMA chain
__device__ __forceinline__ float sigp(float xv) {
    float x2 = xv * xv;
    float t = fmaf(x2, 2.135765e-5f, -2.1081349e-4f);
    t = fmaf(x2, t, 2.0833333e-3f);
    t = fmaf(x2, t, -2.0833333e-2f);
    t = fmaf(x2, t, 0.25f);
    return fmaf(xv, t, 0.5f);
}

#define FULLMASK 0xffffffffu

// ---------------------------------------------------------------------------
// Fused persistent kernel, 148 blocks = 1 per SM:
//   blocks [0,32):   recurrence (warp 7 only; SM otherwise idle -> no contention)
//   blocks [32,148): persistent projection workers (atomic tile counter)
// ---------------------------------------------------------------------------
__global__ __launch_bounds__(FUSED_THREADS)
void fused_kernel(const float* __restrict__ x,
                  const float* __restrict__ Wf, const float* __restrict__ bf, const float* __restrict__ thf,
                  const float* __restrict__ Wi, const float* __restrict__ bi, const float* __restrict__ thi,
                  const float* __restrict__ Wu, const float* __restrict__ bu, const float* __restrict__ thu,
                  const float* __restrict__ Wo, const float* __restrict__ bo, const float* __restrict__ tho,
                  float* __restrict__ out)
{
    const int tid = threadIdx.x;

    if (blockIdx.x >= RECUR_BLOCKS) {
        // ------------------- persistent projection worker -------------------
        __shared__ float xs[64][132];
        __shared__ float ws[DIN][NG];          // ws[j][u*4+g]
        __shared__ float bt[NG];
        __shared__ int   s_tile;

        // stage weights once per block
        for (int i = tid; i < DIN * NG; i += FUSED_THREADS) {
            int j = i >> 4, k = i & 15;
            int u = k >> 2, g = k & 3;
            const float* W = (g == 0) ? Wf : (g == 1) ? Wi : (g == 2) ? Wu : Wo;
            ws[j][k] = W[j * 4 + u];
        }
        if (tid < NG) {
            int u = tid >> 2, g = tid & 3;
            const float* b  = (g == 0) ? bf  : (g == 1) ? bi  : (g == 2) ? bu  : bo;
            const float* th = (g == 0) ? thf : (g == 1) ? thi : (g == 2) ? thu : tho;
            bt[tid] = b[u] + th[u];
        }

        const int r  = tid & 63;
        const int kg = tid >> 6;

        for (;;) {
            if (tid == 0)
                s_tile = atomicAdd(&g_tile, 1);
            __syncthreads();                    // publishes s_tile; separates xs reuse
            const int tileIdx = s_tile;
            if (tileIdx >= PROJ_TILES) break;
            const long rowBase = (long)tileIdx * 64;

            const float4* x4 = (const float4*)x + rowBase * (DIN / 4);
            #pragma unroll
            for (int i = tid; i < 64 * (DIN / 4); i += FUSED_THREADS) {
                float4 v = x4[i];
                int row = i >> 5;
                int c4  = i & 31;
                *(float4*)&xs[row][c4 * 4] = v;
            }
            __syncthreads();

            float a0 = 0.f, a1 = 0.f, a2 = 0.f, a3 = 0.f;
            #pragma unroll
            for (int jj = 0; jj < DIN / 4; jj++) {
                float4 xv = *(const float4*)&xs[r][jj * 4];
                float4 w0 = *(const float4*)&ws[jj * 4 + 0][kg * 4];
                float4 w1 = *(const float4*)&ws[jj * 4 + 1][kg * 4];
                float4 w2 = *(const float4*)&ws[jj * 4 + 2][kg * 4];
                float4 w3 = *(const float4*)&ws[jj * 4 + 3][kg * 4];
                a0 = fmaf(xv.x, w0.x, fmaf(xv.y, w1.x, fmaf(xv.z, w2.x, fmaf(xv.w, w3.x, a0))));
                a1 = fmaf(xv.x, w0.y, fmaf(xv.y, w1.y, fmaf(xv.z, w2.y, fmaf(xv.w, w3.y, a1))));
                a2 = fmaf(xv.x, w0.z, fmaf(xv.y, w1.z, fmaf(xv.z, w2.z, fmaf(xv.w, w3.z, a2))));
                a3 = fmaf(xv.x, w0.w, fmaf(xv.y, w1.w, fmaf(xv.z, w2.w, fmaf(xv.w, w3.w, a3))));
            }
            float4 o;
            o.x = a0 + bt[kg * 4 + 0];
            o.y = a1 + bt[kg * 4 + 1];
            o.z = a2 + bt[kg * 4 + 2];
            o.w = a3 + bt[kg * 4 + 3];
            *(float4*)&g_xproj[(rowBase + r) * NG + kg * 4] = o;

            // publish: stores visible, then bump this t's tile counter
            __threadfence();
            __syncthreads();
            if (tid == 0)
                atomicAdd(&g_done[(int)(rowBase >> 8)], 1);
        }
        return;
    }

    // --------------------------- recurrence ---------------------------
    if (tid < 224) return;                 // warp 7 only; rest of SM stays empty
    const int lane = tid & 31;
    const int u    = lane & 3;
    const int b    = blockIdx.x * 8 + (lane >> 2);

    // Whl[m][g] = W_gate_g[(128+m)*4 + u]
    float Whl[4][4];
    #pragma unroll
    for (int m = 0; m < 4; m++) {
        Whl[m][0] = Wf[(128 + m) * 4 + u];
        Whl[m][1] = Wi[(128 + m) * 4 + u];
        Whl[m][2] = Wu[(128 + m) * 4 + u];
        Whl[m][3] = Wo[(128 + m) * 4 + u];
    }
    const bool ge1 = (u >= 1);
    const bool ge2 = (u >= 2);
    const bool ge3 = (u >= 3);

    float h0 = 0.f, h1 = 0.f, h2 = 0.f, h3 = 0.f;
    float c  = 0.f;

    const float4* xp = (const float4*)g_xproj + ((size_t)b * 4 + u);
    float4 buf[RDEPTH];
    int    fbuf[RDEPTH];
    #pragma unroll
    for (int d = 0; d < RDEPTH; d++) {
        while (*(volatile const int*)&g_done[d] != 4) { }
        buf[d]  = xp[(size_t)d * (BATCH * 4)];
        fbuf[d] = *(volatile const int*)&g_done[d + RDEPTH];
    }

    #pragma unroll 4
    for (int t = 0; t < T_STEPS; t++) {
        const int slot = t & (RDEPTH - 1);

        // verify flag for t+RDEPTH (prefetched RDEPTH steps ago); rare spin if late
        if (fbuf[slot] != 4) {
            while (*(volatile const int*)&g_done[t + RDEPTH] != 4) { }
        }

        float4 zx = buf[slot];
        buf[slot]  = xp[(size_t)(t + RDEPTH) * (BATCH * 4)];
        fbuf[slot] = *(volatile const int*)&g_done[t + 2 * RDEPTH];

        // z_g = zx_g + h . Whl[:,g]  (tree form) then cos
        float a, bb;
        a  = fmaf(h1, Whl[1][0], fmaf(h0, Whl[0][0], zx.x));
        bb = fmaf(h3, Whl[3][0], h2 * Whl[2][0]);
        float q0 = __cosf(a + bb);
        a  = fmaf(h1, Whl[1][1], fmaf(h0, Whl[0][1], zx.y));
        bb = fmaf(h3, Whl[3][1], h2 * Whl[2][1]);
        float q1 = __cosf(a + bb);
        a  = fmaf(h1, Whl[1][2], fmaf(h0, Whl[0][2], zx.z));
        bb = fmaf(h3, Whl[3][2], h2 * Whl[2][2]);
        float q2 = __cosf(a + bb);
        a  = fmaf(h1, Whl[1][3], fmaf(h0, Whl[0][3], zx.w));
        bb = fmaf(h3, Whl[3][3], h2 * Whl[2][3]);
        float q3 = __cosf(a + bb);

        // prefix product across the unit quad: 3 parallel index-shfls per gate,
        // then a 2-level predicated multiply tree
        {
            float s00 = __shfl_sync(FULLMASK, q0, 0, 4);
            float s01 = __shfl_sync(FULLMASK, q0, 1, 4);
            float s02 = __shfl_sync(FULLMASK, q0, 2, 4);
            float s10 = __shfl_sync(FULLMASK, q1, 0, 4);
            float s11 = __shfl_sync(FULLMASK, q1, 1, 4);
            float s12 = __shfl_sync(FULLMASK, q1, 2, 4);
            float s20 = __shfl_sync(FULLMASK, q2, 0, 4);
            float s21 = __shfl_sync(FULLMASK, q2, 1, 4);
            float s22 = __shfl_sync(FULLMASK, q2, 2, 4);
            float s30 = __shfl_sync(FULLMASK, q3, 0, 4);
            float s31 = __shfl_sync(FULLMASK, q3, 1, 4);
            float s32 = __shfl_sync(FULLMASK, q3, 2, 4);
            float m0 = ge1 ? s00 : 1.0f; if (ge2) m0 *= s01;
            float m1 = ge1 ? s10 : 1.0f; if (ge2) m1 *= s11;
            float m2 = ge1 ? s20 : 1.0f; if (ge2) m2 *= s21;
            float m3 = ge1 ? s30 : 1.0f; if (ge2) m3 *= s31;
            q0 *= m0; if (ge3) q0 *= s02;
            q1 *= m1; if (ge3) q1 *= s12;
            q2 *= m2; if (ge3) q2 *= s22;
            q3 *= m3; if (ge3) q3 *= s32;
        }

        // activations: f,i,o on FMA pipe; g via MUFU tanh (overlaps sigp chains)
        float f  = sigp(q0);
        float i  = sigp(q1);
        float gg = tanh_a(q2);
        float o  = sigp(q3);

        c = fmaf(f, c, i * gg);
        float hu = o * tanh_a(c);

        out[((size_t)t * BATCH + b) * 4 + u] = hu;

        // broadcast h within the 4-lane group
        h0 = __shfl_sync(FULLMASK, hu, 0, 4);
        h1 = __shfl_sync(FULLMASK, hu, 1, 4);
        h2 = __shfl_sync(FULLMASK, hu, 2, 4);
        h3 = __shfl_sync(FULLMASK, hu, 3, 4);
    }

    // hx, cx appended after outputs
    float hx = (u == 0) ? h0 : (u == 1) ? h1 : (u == 2) ? h2 : h3;
    out[(size_t)T_STEPS * BATCH * 4 + (size_t)b * 4 + u]                     = hx;
    out[(size_t)T_STEPS * BATCH * 4 + (size_t)BATCH * 4 + (size_t)b * 4 + u] = c;
}

// ---------------------------------------------------------------------------
extern "C" void kernel_launch(void* const* d_in, const int* in_sizes, int n_in,
                              void* d_out, int out_size)
{
    (void)in_sizes; (void)n_in; (void)out_size;
    const float* x   = (const float*)d_in[0];
    const float* Wf  = (const float*)d_in[1];
    const float* bf  = (const float*)d_in[2];
    const float* thf = (const float*)d_in[3];
    const float* Wi  = (const float*)d_in[4];
    const float* bi  = (const float*)d_in[5];
    const float* thi = (const float*)d_in[6];
    const float* Wu  = (const float*)d_in[7];
    const float* bu  = (const float*)d_in[8];
    const float* thu = (const float*)d_in[9];
    const float* Wo  = (const float*)d_in[10];
    const float* bo  = (const float*)d_in[11];
    const float* tho = (const float*)d_in[12];
    float* out = (float*)d_out;

    clear_kernel<<<(T_STEPS + 16 + 255) / 256, 256>>>();
    fused_kernel<<<TOTAL_BLOCKS, FUSED_THREADS>>>(
        x, Wf, bf, thf, Wi, bi, thi, Wu, bu, thu, Wo, bo, tho, out);
}

// round 14
// speedup vs baseline: 1.2142x; 1.2142x over previous
#include <cuda_runtime.h>

#define T_STEPS 2048
#define BATCH   256
#define DIN     128
#define NG      16      // scratch layout k = u*4 + g
#define RDEPTH  4

#define RECUR_BLOCKS 32
#define PROJ_TILES   (T_STEPS * BATCH / 64)   // 8192
#define FUSED_THREADS 256
#define DSMEM_BYTES  (80 * 1024)   // padding to cap occupancy at 2 blocks/SM

// Scratch: x-part projections (+bias+theta folded), layout [t][b][u*4+g]
// Over-allocated by RDEPTH steps so the recurrence prefetch needs no bounds check.
__device__ float g_xproj[(T_STEPS + RDEPTH) * BATCH * NG];
// per-t completion counters (4 proj tiles per t); tail pre-set to "done"
__device__ int g_done[T_STEPS + 16];

// ---------------------------------------------------------------------------
__global__ void clear_kernel()
{
    int i = blockIdx.x * blockDim.x + threadIdx.x;
    if (i < T_STEPS + 16)
        g_done[i] = (i < T_STEPS) ? 0 : 4;
}

// ---------------------------------------------------------------------------
// helpers
// ---------------------------------------------------------------------------
__device__ __forceinline__ float tanh_a(float x) {
    float y;
    asm("tanh.approx.f32 %0, %1;" : "=f"(y) : "f"(x));
    return y;
}
// sigmoid on [-1,1] via odd Taylor poly (err <= ~3e-6): fixed-latency FMA chain
__device__ __forceinline__ float sigp(float xv) {
    float x2 = xv * xv;
    float t = fmaf(x2, 2.135765e-5f, -2.1081349e-4f);
    t = fmaf(x2, t, 2.0833333e-3f);
    t = fmaf(x2, t, -2.0833333e-2f);
    t = fmaf(x2, t, 0.25f);
    return fmaf(xv, t, 0.5f);
}

#define FULLMASK 0xffffffffu

// ---------------------------------------------------------------------------
// Fused kernel (R12 structure): blocks [0,32) = recurrence (warp 7 only);
// rest = one 64-row projection tile each. Dynamic smem padded to 80 KB so at
// most 2 blocks/SM co-reside -> at most 1 proj block on each recurrence SM.
// ---------------------------------------------------------------------------
__global__ __launch_bounds__(FUSED_THREADS)
void fused_kernel(const float* __restrict__ x,
                  const float* __restrict__ Wf, const float* __restrict__ bf, const float* __restrict__ thf,
                  const float* __restrict__ Wi, const float* __restrict__ bi, const float* __restrict__ thi,
                  const float* __restrict__ Wu, const float* __restrict__ bu, const float* __restrict__ thu,
                  const float* __restrict__ Wo, const float* __restrict__ bo, const float* __restrict__ tho,
                  float* __restrict__ out)
{
    const int tid = threadIdx.x;

    if (blockIdx.x >= RECUR_BLOCKS) {
        // ----------------------- projection tile -----------------------
        extern __shared__ unsigned char s_raw[];
        float (*xs)[132] = (float (*)[132])(s_raw);                    // 64*132*4 = 33792 B
        float (*ws)[NG]  = (float (*)[NG])(s_raw + 33792);             // 128*16*4 =  8192 B
        float* bt        = (float*)(s_raw + 33792 + 8192);             // 64 B

        const long tileIdx = blockIdx.x - RECUR_BLOCKS;
        const long rowBase = tileIdx * 64;

        const float4* x4 = (const float4*)x + rowBase * (DIN / 4);
        #pragma unroll
        for (int i = tid; i < 64 * (DIN / 4); i += FUSED_THREADS) {
            float4 v = x4[i];
            int row = i >> 5;
            int c4  = i & 31;
            *(float4*)&xs[row][c4 * 4] = v;
        }
        for (int i = tid; i < DIN * NG; i += FUSED_THREADS) {
            int j = i >> 4, k = i & 15;
            int u = k >> 2, g = k & 3;
            const float* W = (g == 0) ? Wf : (g == 1) ? Wi : (g == 2) ? Wu : Wo;
            ws[j][k] = W[j * 4 + u];
        }
        if (tid < NG) {
            int u = tid >> 2, g = tid & 3;
            const float* b  = (g == 0) ? bf  : (g == 1) ? bi  : (g == 2) ? bu  : bo;
            const float* th = (g == 0) ? thf : (g == 1) ? thi : (g == 2) ? thu : tho;
            bt[tid] = b[u] + th[u];
        }
        __syncthreads();

        const int r  = tid & 63;
        const int kg = tid >> 6;
        float a0 = 0.f, a1 = 0.f, a2 = 0.f, a3 = 0.f;

        #pragma unroll
        for (int jj = 0; jj < DIN / 4; jj++) {
            float4 xv = *(const float4*)&xs[r][jj * 4];
            float4 w0 = *(const float4*)&ws[jj * 4 + 0][kg * 4];
            float4 w1 = *(const float4*)&ws[jj * 4 + 1][kg * 4];
            float4 w2 = *(const float4*)&ws[jj * 4 + 2][kg * 4];
            float4 w3 = *(const float4*)&ws[jj * 4 + 3][kg * 4];
            a0 = fmaf(xv.x, w0.x, fmaf(xv.y, w1.x, fmaf(xv.z, w2.x, fmaf(xv.w, w3.x, a0))));
            a1 = fmaf(xv.x, w0.y, fmaf(xv.y, w1.y, fmaf(xv.z, w2.y, fmaf(xv.w, w3.y, a1))));
            a2 = fmaf(xv.x, w0.z, fmaf(xv.y, w1.z, fmaf(xv.z, w2.z, fmaf(xv.w, w3.z, a2))));
            a3 = fmaf(xv.x, w0.w, fmaf(xv.y, w1.w, fmaf(xv.z, w2.w, fmaf(xv.w, w3.w, a3))));
        }
        float4 o;
        o.x = a0 + bt[kg * 4 + 0];
        o.y = a1 + bt[kg * 4 + 1];
        o.z = a2 + bt[kg * 4 + 2];
        o.w = a3 + bt[kg * 4 + 3];
        *(float4*)&g_xproj[(rowBase + r) * NG + kg * 4] = o;

        // publish: all stores visible, then bump this t's tile counter
        __threadfence();
        __syncthreads();
        if (tid == 0)
            atomicAdd(&g_done[(int)(rowBase >> 8)], 1);
        return;
    }

    // --------------------------- recurrence ---------------------------
    if (tid < 224) return;                 // warp 7 only (highest wid priority)
    const int lane = tid & 31;
    const int u    = lane & 3;
    const int b    = blockIdx.x * 8 + (lane >> 2);

    // Whl[m][g] = W_gate_g[(128+m)*4 + u]
    float Whl[4][4];
    #pragma unroll
    for (int m = 0; m < 4; m++) {
        Whl[m][0] = Wf[(128 + m) * 4 + u];
        Whl[m][1] = Wi[(128 + m) * 4 + u];
        Whl[m][2] = Wu[(128 + m) * 4 + u];
        Whl[m][3] = Wo[(128 + m) * 4 + u];
    }
    const bool ge1 = (u >= 1);
    const bool ge2 = (u >= 2);
    const bool ge3 = (u >= 3);

    float h0 = 0.f, h1 = 0.f, h2 = 0.f, h3 = 0.f;
    float c  = 0.f;

    const float4* xp = (const float4*)g_xproj + ((size_t)b * 4 + u);
    float4 buf[RDEPTH];
    int    fbuf[RDEPTH];
    #pragma unroll
    for (int d = 0; d < RDEPTH; d++) {
        while (*(volatile const int*)&g_done[d] != 4) { }
        buf[d]  = xp[(size_t)d * (BATCH * 4)];
        fbuf[d] = *(volatile const int*)&g_done[d + RDEPTH];
    }

    #pragma unroll 4
    for (int t = 0; t < T_STEPS; t++) {
        const int slot = t & (RDEPTH - 1);

        // verify flag for t+RDEPTH (prefetched RDEPTH steps ago); rare spin if late
        if (fbuf[slot] != 4) {
            while (*(volatile const int*)&g_done[t + RDEPTH] != 4) { }
        }

        float4 zx = buf[slot];
        buf[slot]  = xp[(size_t)(t + RDEPTH) * (BATCH * 4)];
        fbuf[slot] = *(volatile const int*)&g_done[t + 2 * RDEPTH];

        // z_g = zx_g + h . Whl[:,g]  (tree form) then cos
        float a, bb;
        a  = fmaf(h1, Whl[1][0], fmaf(h0, Whl[0][0], zx.x));
        bb = fmaf(h3, Whl[3][0], h2 * Whl[2][0]);
        float q0 = __cosf(a + bb);
        a  = fmaf(h1, Whl[1][1], fmaf(h0, Whl[0][1], zx.y));
        bb = fmaf(h3, Whl[3][1], h2 * Whl[2][1]);
        float q1 = __cosf(a + bb);
        a  = fmaf(h1, Whl[1][2], fmaf(h0, Whl[0][2], zx.z));
        bb = fmaf(h3, Whl[3][2], h2 * Whl[2][2]);
        float q2 = __cosf(a + bb);
        a  = fmaf(h1, Whl[1][3], fmaf(h0, Whl[0][3], zx.w));
        bb = fmaf(h3, Whl[3][3], h2 * Whl[2][3]);
        float q3 = __cosf(a + bb);

        // prefix product across the unit quad: 3 parallel index-shfls per gate,
        // then a 2-level predicated multiply tree
        {
            float s00 = __shfl_sync(FULLMASK, q0, 0, 4);
            float s01 = __shfl_sync(FULLMASK, q0, 1, 4);
            float s02 = __shfl_sync(FULLMASK, q0, 2, 4);
            float s10 = __shfl_sync(FULLMASK, q1, 0, 4);
            float s11 = __shfl_sync(FULLMASK, q1, 1, 4);
            float s12 = __shfl_sync(FULLMASK, q1, 2, 4);
            float s20 = __shfl_sync(FULLMASK, q2, 0, 4);
            float s21 = __shfl_sync(FULLMASK, q2, 1, 4);
            float s22 = __shfl_sync(FULLMASK, q2, 2, 4);
            float s30 = __shfl_sync(FULLMASK, q3, 0, 4);
            float s31 = __shfl_sync(FULLMASK, q3, 1, 4);
            float s32 = __shfl_sync(FULLMASK, q3, 2, 4);
            float m0 = ge1 ? s00 : 1.0f; if (ge2) m0 *= s01;
            float m1 = ge1 ? s10 : 1.0f; if (ge2) m1 *= s11;
            float m2 = ge1 ? s20 : 1.0f; if (ge2) m2 *= s21;
            float m3 = ge1 ? s30 : 1.0f; if (ge2) m3 *= s31;
            q0 *= m0; if (ge3) q0 *= s02;
            q1 *= m1; if (ge3) q1 *= s12;
            q2 *= m2; if (ge3) q2 *= s22;
            q3 *= m3; if (ge3) q3 *= s32;
        }

        // activations: f,i,o on FMA pipe; g via MUFU tanh (overlaps sigp chains)
        float f  = sigp(q0);
        float i  = sigp(q1);
        float gg = tanh_a(q2);
        float o  = sigp(q3);

        c = fmaf(f, c, i * gg);
        float hu = o * tanh_a(c);

        out[((size_t)t * BATCH + b) * 4 + u] = hu;

        // broadcast h within the 4-lane group
        h0 = __shfl_sync(FULLMASK, hu, 0, 4);
        h1 = __shfl_sync(FULLMASK, hu, 1, 4);
        h2 = __shfl_sync(FULLMASK, hu, 2, 4);
        h3 = __shfl_sync(FULLMASK, hu, 3, 4);
    }

    // hx, cx appended after outputs
    float hx = (u == 0) ? h0 : (u == 1) ? h1 : (u == 2) ? h2 : h3;
    out[(size_t)T_STEPS * BATCH * 4 + (size_t)b * 4 + u]                     = hx;
    out[(size_t)T_STEPS * BATCH * 4 + (size_t)BATCH * 4 + (size_t)b * 4 + u] = c;
}

// ---------------------------------------------------------------------------
extern "C" void kernel_launch(void* const* d_in, const int* in_sizes, int n_in,
                              void* d_out, int out_size)
{
    (void)in_sizes; (void)n_in; (void)out_size;
    const float* x   = (const float*)d_in[0];
    const float* Wf  = (const float*)d_in[1];
    const float* bf  = (const float*)d_in[2];
    const float* thf = (const float*)d_in[3];
    const float* Wi  = (const float*)d_in[4];
    const float* bi  = (const float*)d_in[5];
    const float* thi = (const float*)d_in[6];
    const float* Wu  = (const float*)d_in[7];
    const float* bu  = (const float*)d_in[8];
    const float* thu = (const float*)d_in[9];
    const float* Wo  = (const float*)d_in[10];
    const float* bo  = (const float*)d_in[11];
    const float* tho = (const float*)d_in[12];
    float* out = (float*)d_out;

    static int attr_set = 0;
    if (!attr_set) {
        cudaFuncSetAttribute(fused_kernel,
                             cudaFuncAttributeMaxDynamicSharedMemorySize,
                             DSMEM_BYTES);
        attr_set = 1;
    }

    clear_kernel<<<(T_STEPS + 16 + 255) / 256, 256>>>();
    fused_kernel<<<RECUR_BLOCKS + PROJ_TILES, FUSED_THREADS, DSMEM_BYTES>>>(
        x, Wf, bf, thf, Wi, bi, thi, Wu, bu, thu, Wo, bo, tho, out);
}

// round 17
// speedup vs baseline: 2.9064x; 2.3938x over previous
#include <cuda_runtime.h>

#define T_STEPS 2048
#define BATCH   256
#define DIN     128
#define NG      16      // scratch layout k = u*4 + g
#define RDEPTH  4

#define SEGS    16
#define PAYLOAD (T_STEPS / SEGS)    // 128
#define WARMUP  160

// Scratch: x-part projections (+bias+theta folded), layout [t][b][u*4+g]
// Over-allocated by RDEPTH steps so the recurrence prefetch needs no bounds check.
__device__ float g_xproj[(T_STEPS + RDEPTH) * BATCH * NG];

// ---------------------------------------------------------------------------
// Kernel 1: fused 4-gate projection (standalone; R10/R14-proven tile)
// ---------------------------------------------------------------------------
#define TILE_ROWS    64
#define PROJ_THREADS 256

__global__ __launch_bounds__(PROJ_THREADS)
void proj_kernel(const float* __restrict__ x,
                 const float* __restrict__ Wf, const float* __restrict__ bf, const float* __restrict__ thf,
                 const float* __restrict__ Wi, const float* __restrict__ bi, const float* __restrict__ thi,
                 const float* __restrict__ Wu, const float* __restrict__ bu, const float* __restrict__ thu,
                 const float* __restrict__ Wo, const float* __restrict__ bo, const float* __restrict__ tho)
{
    __shared__ float xs[TILE_ROWS][132];
    __shared__ float ws[DIN][NG];          // ws[j][u*4+g]
    __shared__ float bt[NG];

    const int tid = threadIdx.x;
    const long rowBase = (long)blockIdx.x * TILE_ROWS;

    const float4* x4 = (const float4*)x + rowBase * (DIN / 4);
    #pragma unroll
    for (int i = tid; i < TILE_ROWS * (DIN / 4); i += PROJ_THREADS) {
        float4 v = x4[i];
        int row = i >> 5;
        int c4  = i & 31;
        *(float4*)&xs[row][c4 * 4] = v;
    }
    for (int i = tid; i < DIN * NG; i += PROJ_THREADS) {
        int j = i >> 4, k = i & 15;
        int u = k >> 2, g = k & 3;
        const float* W = (g == 0) ? Wf : (g == 1) ? Wi : (g == 2) ? Wu : Wo;
        ws[j][k] = W[j * 4 + u];
    }
    if (tid < NG) {
        int u = tid >> 2, g = tid & 3;
        const float* b  = (g == 0) ? bf  : (g == 1) ? bi  : (g == 2) ? bu  : bo;
        const float* th = (g == 0) ? thf : (g == 1) ? thi : (g == 2) ? thu : tho;
        bt[tid] = b[u] + th[u];
    }
    __syncthreads();

    const int r  = tid & (TILE_ROWS - 1);
    const int kg = tid >> 6;
    float a0 = 0.f, a1 = 0.f, a2 = 0.f, a3 = 0.f;

    #pragma unroll
    for (int jj = 0; jj < DIN / 4; jj++) {
        float4 xv = *(const float4*)&xs[r][jj * 4];
        float4 w0 = *(const float4*)&ws[jj * 4 + 0][kg * 4];
        float4 w1 = *(const float4*)&ws[jj * 4 + 1][kg * 4];
        float4 w2 = *(const float4*)&ws[jj * 4 + 2][kg * 4];
        float4 w3 = *(const float4*)&ws[jj * 4 + 3][kg * 4];
        a0 = fmaf(xv.x, w0.x, fmaf(xv.y, w1.x, fmaf(xv.z, w2.x, fmaf(xv.w, w3.x, a0))));
        a1 = fmaf(xv.x, w0.y, fmaf(xv.y, w1.y, fmaf(xv.z, w2.y, fmaf(xv.w, w3.y, a1))));
        a2 = fmaf(xv.x, w0.z, fmaf(xv.y, w1.z, fmaf(xv.z, w2.z, fmaf(xv.w, w3.z, a2))));
        a3 = fmaf(xv.x, w0.w, fmaf(xv.y, w1.w, fmaf(xv.z, w2.w, fmaf(xv.w, w3.w, a3))));
    }
    float4 o;
    o.x = a0 + bt[kg * 4 + 0];
    o.y = a1 + bt[kg * 4 + 1];
    o.z = a2 + bt[kg * 4 + 2];
    o.w = a3 + bt[kg * 4 + 3];
    *(float4*)&g_xproj[(rowBase + r) * NG + kg * 4] = o;
}

// ---------------------------------------------------------------------------
// Kernel 2: time-parallel recurrence. 16 segments x 128 payload steps, each
// segment warm-started W=160 steps early from c=h=0 (contraction => converged).
// One warp per (segment, 8-batch group); identical R14 step body.
// ---------------------------------------------------------------------------
__device__ __forceinline__ float tanh_a(float x) {
    float y;
    asm("tanh.approx.f32 %0, %1;" : "=f"(y) : "f"(x));
    return y;
}
// sigmoid on [-1,1] via odd Taylor poly (err <= ~3e-6): fixed-latency FMA chain
__device__ __forceinline__ float sigp(float xv) {
    float x2 = xv * xv;
    float t = fmaf(x2, 2.135765e-5f, -2.1081349e-4f);
    t = fmaf(x2, t, 2.0833333e-3f);
    t = fmaf(x2, t, -2.0833333e-2f);
    t = fmaf(x2, t, 0.25f);
    return fmaf(xv, t, 0.5f);
}

#define FULLMASK 0xffffffffu

__global__ __launch_bounds__(32)
void recur_kernel(const float* __restrict__ Wf, const float* __restrict__ Wi,
                  const float* __restrict__ Wu, const float* __restrict__ Wo,
                  float* __restrict__ out)
{
    const int lane = threadIdx.x;
    const int u    = lane & 3;
    const int seg  = blockIdx.x >> 5;                       // 0..15
    const int b    = (blockIdx.x & 31) * 8 + (lane >> 2);   // batch element

    const int tpay   = seg * PAYLOAD;                       // payload start
    const int tstart = (tpay >= WARMUP) ? (tpay - WARMUP) : 0;
    const int tend   = tpay + PAYLOAD;

    // Whl[m][g] = W_gate_g[(128+m)*4 + u]
    float Whl[4][4];
    #pragma unroll
    for (int m = 0; m < 4; m++) {
        Whl[m][0] = Wf[(128 + m) * 4 + u];
        Whl[m][1] = Wi[(128 + m) * 4 + u];
        Whl[m][2] = Wu[(128 + m) * 4 + u];
        Whl[m][3] = Wo[(128 + m) * 4 + u];
    }
    const bool ge1 = (u >= 1);
    const bool ge2 = (u >= 2);
    const bool ge3 = (u >= 3);

    float h0 = 0.f, h1 = 0.f, h2 = 0.f, h3 = 0.f;
    float c  = 0.f;

    const float4* xp = (const float4*)g_xproj + ((size_t)b * 4 + u);
    float4 buf[RDEPTH];
    #pragma unroll
    for (int d = 0; d < RDEPTH; d++)
        buf[d] = xp[(size_t)(tstart + d) * (BATCH * 4)];

    #pragma unroll 4
    for (int t = tstart; t < tend; t++) {
        const int slot = (t - tstart) & (RDEPTH - 1);
        float4 zx = buf[slot];
        buf[slot] = xp[(size_t)(t + RDEPTH) * (BATCH * 4)];  // over-allocated: safe

        // z_g = zx_g + h . Whl[:,g]  (tree form) then cos
        float a, bb;
        a  = fmaf(h1, Whl[1][0], fmaf(h0, Whl[0][0], zx.x));
        bb = fmaf(h3, Whl[3][0], h2 * Whl[2][0]);
        float q0 = __cosf(a + bb);
        a  = fmaf(h1, Whl[1][1], fmaf(h0, Whl[0][1], zx.y));
        bb = fmaf(h3, Whl[3][1], h2 * Whl[2][1]);
        float q1 = __cosf(a + bb);
        a  = fmaf(h1, Whl[1][2], fmaf(h0, Whl[0][2], zx.z));
        bb = fmaf(h3, Whl[3][2], h2 * Whl[2][2]);
        float q2 = __cosf(a + bb);
        a  = fmaf(h1, Whl[1][3], fmaf(h0, Whl[0][3], zx.w));
        bb = fmaf(h3, Whl[3][3], h2 * Whl[2][3]);
        float q3 = __cosf(a + bb);

        // prefix product across the unit quad: 3 parallel index-shfls per gate,
        // then a 2-level predicated multiply tree
        {
            float s00 = __shfl_sync(FULLMASK, q0, 0, 4);
            float s01 = __shfl_sync(FULLMASK, q0, 1, 4);
            float s02 = __shfl_sync(FULLMASK, q0, 2, 4);
            float s10 = __shfl_sync(FULLMASK, q1, 0, 4);
            float s11 = __shfl_sync(FULLMASK, q1, 1, 4);
            float s12 = __shfl_sync(FULLMASK, q1, 2, 4);
            float s20 = __shfl_sync(FULLMASK, q2, 0, 4);
            float s21 = __shfl_sync(FULLMASK, q2, 1, 4);
            float s22 = __shfl_sync(FULLMASK, q2, 2, 4);
            float s30 = __shfl_sync(FULLMASK, q3, 0, 4);
            float s31 = __shfl_sync(FULLMASK, q3, 1, 4);
            float s32 = __shfl_sync(FULLMASK, q3, 2, 4);
            float m0 = ge1 ? s00 : 1.0f; if (ge2) m0 *= s01;
            float m1 = ge1 ? s10 : 1.0f; if (ge2) m1 *= s11;
            float m2 = ge1 ? s20 : 1.0f; if (ge2) m2 *= s21;
            float m3 = ge1 ? s30 : 1.0f; if (ge2) m3 *= s31;
            q0 *= m0; if (ge3) q0 *= s02;
            q1 *= m1; if (ge3) q1 *= s12;
            q2 *= m2; if (ge3) q2 *= s22;
            q3 *= m3; if (ge3) q3 *= s32;
        }

        // activations: f,i,o on FMA pipe; g via MUFU tanh (overlaps sigp chains)
        float f  = sigp(q0);
        float i  = sigp(q1);
        float gg = tanh_a(q2);
        float o  = sigp(q3);

        c = fmaf(f, c, i * gg);
        float hu = o * tanh_a(c);

        if (t >= tpay)                                  // warp-uniform predicate
            out[((size_t)t * BATCH + b) * 4 + u] = hu;

        // broadcast h within the 4-lane group
        h0 = __shfl_sync(FULLMASK, hu, 0, 4);
        h1 = __shfl_sync(FULLMASK, hu, 1, 4);
        h2 = __shfl_sync(FULLMASK, hu, 2, 4);
        h3 = __shfl_sync(FULLMASK, hu, 3, 4);
    }

    // hx, cx appended after outputs: written by the LAST segment only
    if (seg == SEGS - 1) {
        float hx = (u == 0) ? h0 : (u == 1) ? h1 : (u == 2) ? h2 : h3;
        out[(size_t)T_STEPS * BATCH * 4 + (size_t)b * 4 + u]                     = hx;
        out[(size_t)T_STEPS * BATCH * 4 + (size_t)BATCH * 4 + (size_t)b * 4 + u] = c;
    }
}

// ---------------------------------------------------------------------------
extern "C" void kernel_launch(void* const* d_in, const int* in_sizes, int n_in,
                              void* d_out, int out_size)
{
    (void)in_sizes; (void)n_in; (void)out_size;
    const float* x   = (const float*)d_in[0];
    const float* Wf  = (const float*)d_in[1];
    const float* bf  = (const float*)d_in[2];
    const float* thf = (const float*)d_in[3];
    const float* Wi  = (const float*)d_in[4];
    const float* bi  = (const float*)d_in[5];
    const float* thi = (const float*)d_in[6];
    const float* Wu  = (const float*)d_in[7];
    const float* bu  = (const float*)d_in[8];
    const float* thu = (const float*)d_in[9];
    const float* Wo  = (const float*)d_in[10];
    const float* bo  = (const float*)d_in[11];
    const float* tho = (const float*)d_in[12];
    float* out = (float*)d_out;

    proj_kernel<<<(T_STEPS * BATCH) / TILE_ROWS, PROJ_THREADS>>>(
        x, Wf, bf, thf, Wi, bi, thi, Wu, bu, thu, Wo, bo, tho);
    recur_kernel<<<SEGS * (BATCH / 8), 32>>>(Wf, Wi, Wu, Wo, out);
}